// round 8
// baseline (speedup 1.0000x reference)
#include <cuda_runtime.h>
#include <cuda_bf16.h>
#include <cstdint>

// y = x @ W^T + bias, B=K=N=512 fp32.  LNS reference == plain fp32 matmul.
//  1) cvt_kernel: X,W f32 -> bf16 hi/lo pairs in __device__ scratch (once).
//  2) gemm_kernel: 3-term HMMA (xh*wh + xh*wl + xl*wh), fp32 accum,
//     cp.async 3-stage ring, SIX independent accumulator chains + reg-double-
//     buffered ldmatrix so HMMA latency is covered by ILP, not warp count.

constexpr int KDIM = 512;
constexpr int NDIM = 512;
constexpr int BDIM = 512;

// ---- scratch (static device memory; no allocation) ----
__device__ __nv_bfloat16 g_xh[BDIM * KDIM];
__device__ __nv_bfloat16 g_xl[BDIM * KDIM];
__device__ __nv_bfloat16 g_wh[NDIM * KDIM];
__device__ __nv_bfloat16 g_wl[NDIM * KDIM];

// ======================= convert kernel =======================
__global__ __launch_bounds__(256, 8)
void cvt_kernel(const float4* __restrict__ X, const float4* __restrict__ W)
{
    const int i = blockIdx.x * 256 + threadIdx.x;          // float4 index
    const float4* src = blockIdx.y ? W : X;
    uint2* dh = reinterpret_cast<uint2*>(blockIdx.y ? g_wh : g_xh);
    uint2* dl = reinterpret_cast<uint2*>(blockIdx.y ? g_wl : g_xl);

    float4 v = src[i];
    __nv_bfloat162 h0 = __floats2bfloat162_rn(v.x, v.y);
    __nv_bfloat162 h1 = __floats2bfloat162_rn(v.z, v.w);
    __nv_bfloat162 l0 = __floats2bfloat162_rn(v.x - __bfloat162float(h0.x),
                                              v.y - __bfloat162float(h0.y));
    __nv_bfloat162 l1 = __floats2bfloat162_rn(v.z - __bfloat162float(h1.x),
                                              v.w - __bfloat162float(h1.y));
    dh[i] = make_uint2(*reinterpret_cast<uint32_t*>(&h0),
                       *reinterpret_cast<uint32_t*>(&h1));
    dl[i] = make_uint2(*reinterpret_cast<uint32_t*>(&l0),
                       *reinterpret_cast<uint32_t*>(&l1));
}

// ======================= GEMM kernel =======================
constexpr int BM = 64;
constexpr int BN = 32;
constexpr int KC = 128;                  // k per chunk (bf16)
constexpr int NCHUNK = KDIM / KC;        // 4
constexpr int NSTAGE = 3;
constexpr int NTH = 256;

// smem tile row stride: 128 bf16 = 256B data + 16B pad = 272B
constexpr int ROWB = 272;
constexpr int AH_OFF = 0;
constexpr int AL_OFF = BM * ROWB;             // 17408
constexpr int BH_OFF = 2 * BM * ROWB;         // 34816
constexpr int BL_OFF = BH_OFF + BN * ROWB;    // 43520
constexpr int STAGE  = BH_OFF + 2 * BN * ROWB;    // 52224
constexpr int SMEM_TOTAL = NSTAGE * STAGE;        // 156672

__device__ __forceinline__ uint32_t smem_u32(const void* p) {
    uint32_t a;
    asm("{ .reg .u64 t; cvta.to.shared.u64 t, %1; cvt.u32.u64 %0, t; }"
        : "=r"(a) : "l"(p));
    return a;
}

__device__ __forceinline__ void cp16(uint32_t dst, const void* src) {
    asm volatile("cp.async.cg.shared.global [%0], [%1], 16;"
                 :: "r"(dst), "l"(src) : "memory");
}

__device__ __forceinline__ void ldsm_x4(uint32_t* r, uint32_t addr) {
    asm volatile("ldmatrix.sync.aligned.m8n8.x4.shared.b16 {%0,%1,%2,%3}, [%4];"
                 : "=r"(r[0]), "=r"(r[1]), "=r"(r[2]), "=r"(r[3]) : "r"(addr));
}

__device__ __forceinline__ void mma16816(float* c, const uint32_t* a,
                                         uint32_t b0, uint32_t b1) {
    asm volatile(
        "mma.sync.aligned.m16n8k16.row.col.f32.bf16.bf16.f32 "
        "{%0,%1,%2,%3}, {%4,%5,%6,%7}, {%8,%9}, {%0,%1,%2,%3};"
        : "+f"(c[0]), "+f"(c[1]), "+f"(c[2]), "+f"(c[3])
        : "r"(a[0]), "r"(a[1]), "r"(a[2]), "r"(a[3]), "r"(b0), "r"(b1));
}

__global__ __launch_bounds__(NTH, 1)
void gemm_kernel(const float* __restrict__ bias, float* __restrict__ Y)
{
    extern __shared__ char smem[];
    const uint32_t sb = smem_u32(smem);
    const int tid = threadIdx.x;
    const int wid = tid >> 5;
    const int lid = tid & 31;
    const int wm = wid >> 1;              // 0..3
    const int wn = wid & 1;               // 0..1
    const int block_m = blockIdx.y * BM;
    const int block_n = blockIdx.x * BN;

    // producer mapping: transfer idx -> (row, 16B-col)
    const int p_row = tid >> 4;           // 0..15 (+16 per iter)
    const int p_c   = tid & 15;           // 16B column 0..15

    const __nv_bfloat16* xh = g_xh + (block_m + p_row) * KDIM + p_c * 8;
    const __nv_bfloat16* xl = g_xl + (block_m + p_row) * KDIM + p_c * 8;
    const __nv_bfloat16* wh = g_wh + (block_n + p_row) * KDIM + p_c * 8;
    const __nv_bfloat16* wl = g_wl + (block_n + p_row) * KDIM + p_c * 8;
    const uint32_t p_st = (uint32_t)(p_row * ROWB + p_c * 16);

    // ldmatrix lane addressing (byte offsets within tile)
    const uint32_t a_ld = (uint32_t)((wm * 16 + (lid & 15)) * ROWB + (lid >> 4) * 16);
    const uint32_t b_ld = (uint32_t)((wn * 16 + ((lid & 7) | ((lid >> 4) << 3))) * ROWB
                                     + (((lid >> 3) & 1) * 16));

    // Six independent accumulator chains: {hh,hl,lh} x {n8 block 0,1}.
    float chh0[4] = {}, chh1[4] = {};
    float chl0[4] = {}, chl1[4] = {};
    float clh0[4] = {}, clh1[4] = {};

    auto issue = [&](int chunk) {
        const uint32_t st = sb + (chunk % NSTAGE) * STAGE;
        const int kb = chunk * KC;
        #pragma unroll
        for (int r = 0; r < 4; ++r) {       // A: 64 rows x 16 transfers
            const int ro = r * 16;
            cp16(st + AH_OFF + p_st + ro * ROWB, xh + kb + ro * KDIM);
            cp16(st + AL_OFF + p_st + ro * ROWB, xl + kb + ro * KDIM);
        }
        #pragma unroll
        for (int r = 0; r < 2; ++r) {       // B: 32 rows x 16 transfers
            const int ro = r * 16;
            cp16(st + BH_OFF + p_st + ro * ROWB, wh + kb + ro * KDIM);
            cp16(st + BL_OFF + p_st + ro * ROWB, wl + kb + ro * KDIM);
        }
        asm volatile("cp.async.commit_group;" ::: "memory");
    };

    issue(0);

    for (int i = 0; i < NCHUNK; ++i) {
        if (i + 1 < NCHUNK) {
            issue(i + 1);
            asm volatile("cp.async.wait_group 1;" ::: "memory");
        } else {
            asm volatile("cp.async.wait_group 0;" ::: "memory");
        }
        __syncthreads();

        const uint32_t st = sb + (i % NSTAGE) * STAGE;

        // Register double-buffered fragments: load step s+1 while s computes.
        uint32_t ah[2][4], al[2][4], bh[2][4], bl[2][4];
        ldsm_x4(ah[0], st + AH_OFF + a_ld);
        ldsm_x4(al[0], st + AL_OFF + a_ld);
        ldsm_x4(bh[0], st + BH_OFF + b_ld);
        ldsm_x4(bl[0], st + BL_OFF + b_ld);

        #pragma unroll
        for (int s = 0; s < KC / 16; ++s) {
            const int cur = s & 1;
            if (s + 1 < KC / 16) {
                const int nxt = cur ^ 1;
                ldsm_x4(ah[nxt], st + AH_OFF + a_ld + (s + 1) * 32);
                ldsm_x4(al[nxt], st + AL_OFF + a_ld + (s + 1) * 32);
                ldsm_x4(bh[nxt], st + BH_OFF + b_ld + (s + 1) * 32);
                ldsm_x4(bl[nxt], st + BL_OFF + b_ld + (s + 1) * 32);
            }
            // 6 mutually independent MMAs per step.
            mma16816(chh0, ah[cur], bh[cur][0], bh[cur][1]);
            mma16816(chh1, ah[cur], bh[cur][2], bh[cur][3]);
            mma16816(chl0, ah[cur], bl[cur][0], bl[cur][1]);
            mma16816(chl1, ah[cur], bl[cur][2], bl[cur][3]);
            mma16816(clh0, al[cur], bh[cur][0], bh[cur][1]);
            mma16816(clh1, al[cur], bh[cur][2], bh[cur][3]);
        }
        // no trailing sync: 3-stage ring; buffer being overwritten next was
        // last read two chunks ago, fenced by the sync above.
    }

    // epilogue: combine terms, add bias, store
    const int row0 = block_m + wm * 16 + (lid >> 2);
    const int coln = block_n + wn * 16 + 2 * (lid & 3);
    float c0[4], c1[4];
    #pragma unroll
    for (int j = 0; j < 4; ++j) {
        c0[j] = chh0[j] + chl0[j] + clh0[j];
        c1[j] = chh1[j] + chl1[j] + clh1[j];
    }
    #pragma unroll
    for (int j = 0; j < 2; ++j) {
        const float* cc = j ? c1 : c0;
        const int n = coln + j * 8;
        float2 bv = *reinterpret_cast<const float2*>(bias + n);
        *reinterpret_cast<float2*>(Y + row0 * NDIM + n) =
            make_float2(cc[0] + bv.x, cc[1] + bv.y);
        *reinterpret_cast<float2*>(Y + (row0 + 8) * NDIM + n) =
            make_float2(cc[2] + bv.x, cc[3] + bv.y);
    }
}

extern "C" void kernel_launch(void* const* d_in, const int* in_sizes, int n_in,
                              void* d_out, int out_size)
{
    const float* x    = (const float*)d_in[0];   // [512, 512]
    const float* w    = (const float*)d_in[1];   // [512, 512] (N, K)
    const float* bias = (const float*)d_in[2];   // [512]
    float* y = (float*)d_out;                    // [512, 512]

    cvt_kernel<<<dim3(KDIM * BDIM / 4 / 256, 2), 256>>>(
        (const float4*)x, (const float4*)w);

    cudaFuncSetAttribute(gemm_kernel,
                         cudaFuncAttributeMaxDynamicSharedMemorySize, SMEM_TOTAL);
    dim3 grid(NDIM / BN, BDIM / BM);             // (16, 8) = 128 CTAs, one wave
    gemm_kernel<<<grid, NTH, SMEM_TOTAL>>>(bias, y);
}

// round 10
// speedup vs baseline: 1.1378x; 1.1378x over previous
#include <cuda_runtime.h>
#include <cuda_bf16.h>
#include <cstdint>

// y = x @ W^T + bias, B=K=N=512 fp32.  LNS reference == plain fp32 matmul.
//  1) cvt_kernel: X,W f32 -> bf16 hi/lo pairs in __device__ scratch (once).
//  2) gemm_kernel: 3-term HMMA (xh*wh + xh*wl + xl*wh), fp32 accum.
//     512 threads/CTA (16 warps = 4/SMSP) with k-split-2 across warp halves:
//     doubles latency coverage on the legacy mma.sync path without changing
//     the balanced 128-CTA wave. smem reduction merges the k-halves.

constexpr int KDIM = 512;
constexpr int NDIM = 512;
constexpr int BDIM = 512;

// ---- scratch (static device memory; no allocation) ----
__device__ __nv_bfloat16 g_xh[BDIM * KDIM];
__device__ __nv_bfloat16 g_xl[BDIM * KDIM];
__device__ __nv_bfloat16 g_wh[NDIM * KDIM];
__device__ __nv_bfloat16 g_wl[NDIM * KDIM];

// ======================= convert kernel =======================
__global__ __launch_bounds__(256, 8)
void cvt_kernel(const float4* __restrict__ X, const float4* __restrict__ W)
{
    const int i = blockIdx.x * 256 + threadIdx.x;          // float4 index
    const float4* src = blockIdx.y ? W : X;
    uint2* dh = reinterpret_cast<uint2*>(blockIdx.y ? g_wh : g_xh);
    uint2* dl = reinterpret_cast<uint2*>(blockIdx.y ? g_wl : g_xl);

    float4 v = src[i];
    __nv_bfloat162 h0 = __floats2bfloat162_rn(v.x, v.y);
    __nv_bfloat162 h1 = __floats2bfloat162_rn(v.z, v.w);
    __nv_bfloat162 l0 = __floats2bfloat162_rn(v.x - __bfloat162float(h0.x),
                                              v.y - __bfloat162float(h0.y));
    __nv_bfloat162 l1 = __floats2bfloat162_rn(v.z - __bfloat162float(h1.x),
                                              v.w - __bfloat162float(h1.y));
    dh[i] = make_uint2(*reinterpret_cast<uint32_t*>(&h0),
                       *reinterpret_cast<uint32_t*>(&h1));
    dl[i] = make_uint2(*reinterpret_cast<uint32_t*>(&l0),
                       *reinterpret_cast<uint32_t*>(&l1));
}

// ======================= GEMM kernel =======================
constexpr int BM = 64;
constexpr int BN = 32;
constexpr int KC = 128;                  // k per chunk (bf16)
constexpr int NCHUNK = KDIM / KC;        // 4
constexpr int NSTAGE = 3;
constexpr int NTH = 512;                 // 16 warps: 4x2 warp grid x k-split 2

// smem tile row stride: 128 bf16 = 256B data + 16B pad = 272B
constexpr int ROWB = 272;
constexpr int AH_OFF = 0;
constexpr int AL_OFF = BM * ROWB;             // 17408
constexpr int BH_OFF = 2 * BM * ROWB;         // 34816
constexpr int BL_OFF = BH_OFF + BN * ROWB;    // 43520
constexpr int STAGE  = BH_OFF + 2 * BN * ROWB;    // 52224
constexpr int SMEM_TOTAL = NSTAGE * STAGE;        // 156672

__device__ __forceinline__ uint32_t smem_u32(const void* p) {
    uint32_t a;
    asm("{ .reg .u64 t; cvta.to.shared.u64 t, %1; cvt.u32.u64 %0, t; }"
        : "=r"(a) : "l"(p));
    return a;
}

__device__ __forceinline__ void cp16(uint32_t dst, const void* src) {
    asm volatile("cp.async.cg.shared.global [%0], [%1], 16;"
                 :: "r"(dst), "l"(src) : "memory");
}

__device__ __forceinline__ void ldsm_x4(uint32_t* r, uint32_t addr) {
    asm volatile("ldmatrix.sync.aligned.m8n8.x4.shared.b16 {%0,%1,%2,%3}, [%4];"
                 : "=r"(r[0]), "=r"(r[1]), "=r"(r[2]), "=r"(r[3]) : "r"(addr));
}

__device__ __forceinline__ void mma16816(float* c, const uint32_t* a,
                                         uint32_t b0, uint32_t b1) {
    asm volatile(
        "mma.sync.aligned.m16n8k16.row.col.f32.bf16.bf16.f32 "
        "{%0,%1,%2,%3}, {%4,%5,%6,%7}, {%8,%9}, {%0,%1,%2,%3};"
        : "+f"(c[0]), "+f"(c[1]), "+f"(c[2]), "+f"(c[3])
        : "r"(a[0]), "r"(a[1]), "r"(a[2]), "r"(a[3]), "r"(b0), "r"(b1));
}

__global__ __launch_bounds__(NTH, 1)
void gemm_kernel(const float* __restrict__ bias, float* __restrict__ Y)
{
    extern __shared__ char smem[];
    const uint32_t sb = smem_u32(smem);
    const int tid = threadIdx.x;
    const int wid = tid >> 5;
    const int lid = tid & 31;
    const int wm = wid & 3;               // 0..3  (m tile of 16)
    const int wn = (wid >> 2) & 1;        // 0..1  (n tile of 16)
    const int ks = wid >> 3;              // 0..1  (k-split half)
    const int block_m = blockIdx.y * BM;
    const int block_n = blockIdx.x * BN;

    // producer mapping: 512 threads; tid>>4 = row 0..31 (+32), tid&15 = 16B col
    const int p_row = tid >> 4;
    const int p_c   = tid & 15;

    const __nv_bfloat16* xh = g_xh + (block_m + p_row) * KDIM + p_c * 8;
    const __nv_bfloat16* xl = g_xl + (block_m + p_row) * KDIM + p_c * 8;
    const __nv_bfloat16* wh = g_wh + (block_n + p_row) * KDIM + p_c * 8;
    const __nv_bfloat16* wl = g_wl + (block_n + p_row) * KDIM + p_c * 8;
    const uint32_t p_st = (uint32_t)(p_row * ROWB + p_c * 16);

    // ldmatrix lane addressing (byte offsets within tile)
    const uint32_t a_ld = (uint32_t)((wm * 16 + (lid & 15)) * ROWB + (lid >> 4) * 16);
    const uint32_t b_ld = (uint32_t)((wn * 16 + ((lid & 7) | ((lid >> 4) << 3))) * ROWB
                                     + (((lid >> 3) & 1) * 16));

    // Six independent accumulator chains: {hh,hl,lh} x {n8 block 0,1}.
    float chh0[4] = {}, chh1[4] = {};
    float chl0[4] = {}, chl1[4] = {};
    float clh0[4] = {}, clh1[4] = {};

    auto issue = [&](int chunk) {
        const uint32_t st = sb + (chunk % NSTAGE) * STAGE;
        const int kb = chunk * KC;
        #pragma unroll
        for (int r = 0; r < 2; ++r) {       // A: 64 rows, 32 rows/pass
            const int ro = r * 32;
            cp16(st + AH_OFF + p_st + ro * ROWB, xh + kb + ro * KDIM);
            cp16(st + AL_OFF + p_st + ro * ROWB, xl + kb + ro * KDIM);
        }
        if (p_row < 32) {                   // B: 32 rows (all threads map, 1 pass)
            cp16(st + BH_OFF + p_st, wh + kb);
            cp16(st + BL_OFF + p_st, wl + kb);
        }
        asm volatile("cp.async.commit_group;" ::: "memory");
    };

    issue(0);

    for (int i = 0; i < NCHUNK; ++i) {
        if (i + 1 < NCHUNK) {
            issue(i + 1);
            asm volatile("cp.async.wait_group 1;" ::: "memory");
        } else {
            asm volatile("cp.async.wait_group 0;" ::: "memory");
        }
        __syncthreads();

        const uint32_t st = sb + (i % NSTAGE) * STAGE;

        // k-split: this warp handles steps s = ks, ks+2, ks+4, ks+6.
        #pragma unroll
        for (int j = 0; j < KC / 32; ++j) {
            const int s = ks + 2 * j;
            uint32_t ah[4], al[4], bh[4], bl[4];
            ldsm_x4(ah, st + AH_OFF + a_ld + s * 32);
            ldsm_x4(al, st + AL_OFF + a_ld + s * 32);
            ldsm_x4(bh, st + BH_OFF + b_ld + s * 32);
            ldsm_x4(bl, st + BL_OFF + b_ld + s * 32);

            mma16816(chh0, ah, bh[0], bh[1]);
            mma16816(chh1, ah, bh[2], bh[3]);
            mma16816(chl0, ah, bl[0], bl[1]);
            mma16816(chl1, ah, bl[2], bl[3]);
            mma16816(clh0, al, bh[0], bh[1]);
            mma16816(clh1, al, bh[2], bh[3]);
        }
        // no trailing sync: 3-stage ring; the stage written by the next
        // issue() was last read two chunks ago, fenced by the sync above.
    }

    // combine the 3 split terms locally
    float c0[4], c1[4];
    #pragma unroll
    for (int j = 0; j < 4; ++j) {
        c0[j] = chh0[j] + chl0[j] + clh0[j];
        c1[j] = chh1[j] + chl1[j] + clh1[j];
    }

    // k-split reduction via smem scratch in stage-1 region (free: last chunk
    // computed on stage 0, and no further cp.async writes occur).
    float* scratch = reinterpret_cast<float*>(smem + STAGE);
    const int slot = ((wid & 7) * 32 + lid) * 8;
    if (ks == 1) {
        #pragma unroll
        for (int j = 0; j < 4; ++j) {
            scratch[slot + j]     = c0[j];
            scratch[slot + 4 + j] = c1[j];
        }
    }
    __syncthreads();

    if (ks == 0) {
        #pragma unroll
        for (int j = 0; j < 4; ++j) {
            c0[j] += scratch[slot + j];
            c1[j] += scratch[slot + 4 + j];
        }
        // epilogue: add bias, store
        const int row0 = block_m + wm * 16 + (lid >> 2);
        const int coln = block_n + wn * 16 + 2 * (lid & 3);
        #pragma unroll
        for (int j = 0; j < 2; ++j) {
            const float* cc = j ? c1 : c0;
            const int n = coln + j * 8;
            float2 bv = *reinterpret_cast<const float2*>(bias + n);
            *reinterpret_cast<float2*>(Y + row0 * NDIM + n) =
                make_float2(cc[0] + bv.x, cc[1] + bv.y);
            *reinterpret_cast<float2*>(Y + (row0 + 8) * NDIM + n) =
                make_float2(cc[2] + bv.x, cc[3] + bv.y);
        }
    }
}

extern "C" void kernel_launch(void* const* d_in, const int* in_sizes, int n_in,
                              void* d_out, int out_size)
{
    const float* x    = (const float*)d_in[0];   // [512, 512]
    const float* w    = (const float*)d_in[1];   // [512, 512] (N, K)
    const float* bias = (const float*)d_in[2];   // [512]
    float* y = (float*)d_out;                    // [512, 512]

    cvt_kernel<<<dim3(KDIM * BDIM / 4 / 256, 2), 256>>>(
        (const float4*)x, (const float4*)w);

    cudaFuncSetAttribute(gemm_kernel,
                         cudaFuncAttributeMaxDynamicSharedMemorySize, SMEM_TOTAL);
    dim3 grid(NDIM / BN, BDIM / BM);             // (16, 8) = 128 CTAs, one wave
    gemm_kernel<<<grid, NTH, SMEM_TOTAL>>>(bias, y);
}

// round 11
// speedup vs baseline: 1.3275x; 1.1667x over previous
#include <cuda_runtime.h>
#include <cuda_fp16.h>
#include <cstdint>

// y = x @ W^T + bias, B=K=N=512 fp32.  LNS reference == plain fp32 matmul.
// Legacy mma.sync on sm_103a is per-instruction throughput-bound (~43cyc/mma
// per SMSP, invariant to ILP/occupancy) -> minimize MMA count.
// fp16 asymmetric split: xh+xl = x (22-bit), wh = fp16(w) (11-bit).
//   y ~= xh*wh + xl*wh = x*wh ; only error = w rounding ~2.8e-4 rel (<1e-3).
// 2 MMA terms instead of 3 -> 2/3 the instructions of the bf16 3-term kernel.

constexpr int KDIM = 512;
constexpr int NDIM = 512;
constexpr int BDIM = 512;

// ---- scratch (static device memory; no allocation) ----
__device__ __half g_xh[BDIM * KDIM];
__device__ __half g_xl[BDIM * KDIM];
__device__ __half g_wh[NDIM * KDIM];

// ======================= convert kernel =======================
__global__ __launch_bounds__(256, 8)
void cvt_kernel(const float4* __restrict__ X, const float4* __restrict__ W)
{
    const int i = blockIdx.x * 256 + threadIdx.x;          // float4 index
    if (blockIdx.y) {                                      // W -> wh only
        float4 v = W[i];
        __half2 h0 = __floats2half2_rn(v.x, v.y);
        __half2 h1 = __floats2half2_rn(v.z, v.w);
        reinterpret_cast<uint2*>(g_wh)[i] =
            make_uint2(*reinterpret_cast<uint32_t*>(&h0),
                       *reinterpret_cast<uint32_t*>(&h1));
    } else {                                               // X -> xh, xl
        float4 v = X[i];
        __half2 h0 = __floats2half2_rn(v.x, v.y);
        __half2 h1 = __floats2half2_rn(v.z, v.w);
        __half2 l0 = __floats2half2_rn(v.x - __half2float(h0.x),
                                       v.y - __half2float(h0.y));
        __half2 l1 = __floats2half2_rn(v.z - __half2float(h1.x),
                                       v.w - __half2float(h1.y));
        reinterpret_cast<uint2*>(g_xh)[i] =
            make_uint2(*reinterpret_cast<uint32_t*>(&h0),
                       *reinterpret_cast<uint32_t*>(&h1));
        reinterpret_cast<uint2*>(g_xl)[i] =
            make_uint2(*reinterpret_cast<uint32_t*>(&l0),
                       *reinterpret_cast<uint32_t*>(&l1));
    }
}

// ======================= GEMM kernel =======================
constexpr int BM = 64;
constexpr int BN = 32;
constexpr int KC = 128;                  // k per chunk (fp16)
constexpr int NCHUNK = KDIM / KC;        // 4
constexpr int NSTAGE = 3;
constexpr int NTH = 256;

// smem tile row stride: 128 fp16 = 256B data + 16B pad = 272B
constexpr int ROWB = 272;
constexpr int AH_OFF = 0;
constexpr int AL_OFF = BM * ROWB;             // 17408
constexpr int BH_OFF = 2 * BM * ROWB;         // 34816
constexpr int STAGE  = BH_OFF + BN * ROWB;    // 43520
constexpr int SMEM_TOTAL = NSTAGE * STAGE;    // 130560

__device__ __forceinline__ uint32_t smem_u32(const void* p) {
    uint32_t a;
    asm("{ .reg .u64 t; cvta.to.shared.u64 t, %1; cvt.u32.u64 %0, t; }"
        : "=r"(a) : "l"(p));
    return a;
}

__device__ __forceinline__ void cp16(uint32_t dst, const void* src) {
    asm volatile("cp.async.cg.shared.global [%0], [%1], 16;"
                 :: "r"(dst), "l"(src) : "memory");
}

__device__ __forceinline__ void ldsm_x4(uint32_t* r, uint32_t addr) {
    asm volatile("ldmatrix.sync.aligned.m8n8.x4.shared.b16 {%0,%1,%2,%3}, [%4];"
                 : "=r"(r[0]), "=r"(r[1]), "=r"(r[2]), "=r"(r[3]) : "r"(addr));
}

__device__ __forceinline__ void mma16816(float* c, const uint32_t* a,
                                         uint32_t b0, uint32_t b1) {
    asm volatile(
        "mma.sync.aligned.m16n8k16.row.col.f32.f16.f16.f32 "
        "{%0,%1,%2,%3}, {%4,%5,%6,%7}, {%8,%9}, {%0,%1,%2,%3};"
        : "+f"(c[0]), "+f"(c[1]), "+f"(c[2]), "+f"(c[3])
        : "r"(a[0]), "r"(a[1]), "r"(a[2]), "r"(a[3]), "r"(b0), "r"(b1));
}

__global__ __launch_bounds__(NTH, 1)
void gemm_kernel(const float* __restrict__ bias, float* __restrict__ Y)
{
    extern __shared__ char smem[];
    const uint32_t sb = smem_u32(smem);
    const int tid = threadIdx.x;
    const int wid = tid >> 5;
    const int lid = tid & 31;
    const int wm = wid >> 1;              // 0..3  (m tile of 16)
    const int wn = wid & 1;               // 0..1  (n tile of 16)
    const int block_m = blockIdx.y * BM;
    const int block_n = blockIdx.x * BN;

    // producer mapping: transfer idx -> (row, 16B-col)
    const int p_row = tid >> 4;           // 0..15 (+16 per pass)
    const int p_c   = tid & 15;           // 16B column 0..15

    const __half* xh = g_xh + (block_m + p_row) * KDIM + p_c * 8;
    const __half* xl = g_xl + (block_m + p_row) * KDIM + p_c * 8;
    const __half* wh = g_wh + (block_n + p_row) * KDIM + p_c * 8;
    const uint32_t p_st = (uint32_t)(p_row * ROWB + p_c * 16);

    // ldmatrix lane addressing (byte offsets within tile)
    const uint32_t a_ld = (uint32_t)((wm * 16 + (lid & 15)) * ROWB + (lid >> 4) * 16);
    const uint32_t b_ld = (uint32_t)((wn * 16 + ((lid & 7) | ((lid >> 4) << 3))) * ROWB
                                     + (((lid >> 3) & 1) * 16));

    // Four independent accumulator chains: {hh, lh} x {n8 block 0,1}.
    float chh0[4] = {}, chh1[4] = {};
    float clh0[4] = {}, clh1[4] = {};

    auto issue = [&](int chunk) {
        const uint32_t st = sb + (chunk % NSTAGE) * STAGE;
        const int kb = chunk * KC;
        #pragma unroll
        for (int r = 0; r < 4; ++r) {       // A: 64 rows x 16 transfers
            const int ro = r * 16;
            cp16(st + AH_OFF + p_st + ro * ROWB, xh + kb + ro * KDIM);
            cp16(st + AL_OFF + p_st + ro * ROWB, xl + kb + ro * KDIM);
        }
        #pragma unroll
        for (int r = 0; r < 2; ++r) {       // B: 32 rows x 16 transfers
            const int ro = r * 16;
            cp16(st + BH_OFF + p_st + ro * ROWB, wh + kb + ro * KDIM);
        }
        asm volatile("cp.async.commit_group;" ::: "memory");
    };

    issue(0);

    for (int i = 0; i < NCHUNK; ++i) {
        if (i + 1 < NCHUNK) {
            issue(i + 1);
            asm volatile("cp.async.wait_group 1;" ::: "memory");
        } else {
            asm volatile("cp.async.wait_group 0;" ::: "memory");
        }
        __syncthreads();

        const uint32_t st = sb + (i % NSTAGE) * STAGE;

        #pragma unroll
        for (int s = 0; s < KC / 16; ++s) {
            uint32_t ah[4], al[4], bh[4];
            ldsm_x4(ah, st + AH_OFF + a_ld + s * 32);
            ldsm_x4(al, st + AL_OFF + a_ld + s * 32);
            ldsm_x4(bh, st + BH_OFF + b_ld + s * 32);

            mma16816(chh0, ah, bh[0], bh[1]);
            mma16816(chh1, ah, bh[2], bh[3]);
            mma16816(clh0, al, bh[0], bh[1]);
            mma16816(clh1, al, bh[2], bh[3]);
        }
        // no trailing sync: 3-stage ring; the stage written by the next
        // issue() was last read two chunks ago, fenced by the sync above.
    }

    // epilogue: combine terms, add bias, store
    const int row0 = block_m + wm * 16 + (lid >> 2);
    const int coln = block_n + wn * 16 + 2 * (lid & 3);
    float c0[4], c1[4];
    #pragma unroll
    for (int j = 0; j < 4; ++j) {
        c0[j] = chh0[j] + clh0[j];
        c1[j] = chh1[j] + clh1[j];
    }
    #pragma unroll
    for (int j = 0; j < 2; ++j) {
        const float* cc = j ? c1 : c0;
        const int n = coln + j * 8;
        float2 bv = *reinterpret_cast<const float2*>(bias + n);
        *reinterpret_cast<float2*>(Y + row0 * NDIM + n) =
            make_float2(cc[0] + bv.x, cc[1] + bv.y);
        *reinterpret_cast<float2*>(Y + (row0 + 8) * NDIM + n) =
            make_float2(cc[2] + bv.x, cc[3] + bv.y);
    }
}

extern "C" void kernel_launch(void* const* d_in, const int* in_sizes, int n_in,
                              void* d_out, int out_size)
{
    const float* x    = (const float*)d_in[0];   // [512, 512]
    const float* w    = (const float*)d_in[1];   // [512, 512] (N, K)
    const float* bias = (const float*)d_in[2];   // [512]
    float* y = (float*)d_out;                    // [512, 512]

    cvt_kernel<<<dim3(KDIM * BDIM / 4 / 256, 2), 256>>>(
        (const float4*)x, (const float4*)w);

    cudaFuncSetAttribute(gemm_kernel,
                         cudaFuncAttributeMaxDynamicSharedMemorySize, SMEM_TOTAL);
    dim3 grid(NDIM / BN, BDIM / BM);             // (16, 8) = 128 CTAs, one wave
    gemm_kernel<<<grid, NTH, SMEM_TOTAL>>>(bias, y);
}

// round 13
// speedup vs baseline: 1.6753x; 1.2620x over previous
#include <cuda_runtime.h>
#include <cuda_fp16.h>
#include <cstdint>

// y = x @ W^T + bias, B=K=N=512 fp32.  LNS reference == plain fp32 matmul.
// Single-term fp16 HMMA: y ~= fp16(x) @ fp16(w)^T, fp32 accumulate.
//   rounding error ~2.9e-4 rel (budget 1e-3; r11 measured the w-only half
//   of this at 2.06e-4).
// ONE kernel: f32 LDG -> register cvt -> STS fp16, double-buffered smem,
// one __syncthreads per chunk, register prefetch overlaps compute.

constexpr int KDIM = 512;
constexpr int NDIM = 512;
constexpr int BDIM = 512;

constexpr int BM = 64;
constexpr int BN = 32;
constexpr int KC = 128;                  // k per chunk
constexpr int NCHUNK = KDIM / KC;        // 4
constexpr int NTH = 256;

// smem row stride: 128 fp16 = 256B + 16B pad = 272B (68 words; 68 mod 32 = 4
// -> 8-row ldmatrix phases hit disjoint bank quads).
constexpr int ROWB = 272;
constexpr int A_OFF = 0;
constexpr int B_OFF = BM * ROWB;              // 17408
constexpr int STAGE = B_OFF + BN * ROWB;      // 26112
constexpr int SMEM_TOTAL = 2 * STAGE;         // 52224

__device__ __forceinline__ uint32_t smem_u32(const void* p) {
    uint32_t a;
    asm("{ .reg .u64 t; cvta.to.shared.u64 t, %1; cvt.u32.u64 %0, t; }"
        : "=r"(a) : "l"(p));
    return a;
}

__device__ __forceinline__ void ldsm_x4(uint32_t* r, uint32_t addr) {
    asm volatile("ldmatrix.sync.aligned.m8n8.x4.shared.b16 {%0,%1,%2,%3}, [%4];"
                 : "=r"(r[0]), "=r"(r[1]), "=r"(r[2]), "=r"(r[3]) : "r"(addr));
}

__device__ __forceinline__ void mma16816(float* c, const uint32_t* a,
                                         uint32_t b0, uint32_t b1) {
    asm volatile(
        "mma.sync.aligned.m16n8k16.row.col.f32.f16.f16.f32 "
        "{%0,%1,%2,%3}, {%4,%5,%6,%7}, {%8,%9}, {%0,%1,%2,%3};"
        : "+f"(c[0]), "+f"(c[1]), "+f"(c[2]), "+f"(c[3])
        : "r"(a[0]), "r"(a[1]), "r"(a[2]), "r"(a[3]), "r"(b0), "r"(b1));
}

// float4 -> 4 fp16 (8 bytes) store.
__device__ __forceinline__ void cvt_sts(char* smem, uint32_t byte_off, float4 v) {
    __half2 h0 = __floats2half2_rn(v.x, v.y);
    __half2 h1 = __floats2half2_rn(v.z, v.w);
    *reinterpret_cast<uint2*>(smem + byte_off) =
        make_uint2(*reinterpret_cast<uint32_t*>(&h0),
                   *reinterpret_cast<uint32_t*>(&h1));
}

__global__ __launch_bounds__(NTH, 1)
void lns_linear_kernel(const float* __restrict__ X,
                       const float* __restrict__ W,
                       const float* __restrict__ bias,
                       float* __restrict__ Y)
{
    extern __shared__ char smem[];
    const uint32_t sb = smem_u32(smem);
    const int tid = threadIdx.x;
    const int wid = tid >> 5;
    const int lid = tid & 31;
    const int wm = wid >> 1;              // 0..3  (m tile of 16)
    const int wn = wid & 1;               // 0..1  (n tile of 16)
    const int block_m = blockIdx.y * BM;
    const int block_n = blockIdx.x * BN;

    // producer mapping (per chunk = 64x128 A f32, 32x128 B f32):
    // A: row = tid>>2 (0..63), float4 slots (tid&3)+4r, r=0..7  -> 8 float4
    // B: row = tid>>3 (0..31), float4 slots (tid&7)+8r, r=0..3  -> 4 float4
    const int a_row = tid >> 2, a_c = tid & 3;
    const int b_row = tid >> 3, b_c = tid & 7;
    const float* Aptr = X + (block_m + a_row) * KDIM + a_c * 4;
    const float* Bptr = W + (block_n + b_row) * KDIM + b_c * 4;
    const uint32_t a_st = (uint32_t)(a_row * ROWB + a_c * 8);   // +32B per slot4
    const uint32_t b_st = (uint32_t)(b_row * ROWB + b_c * 8);   // +64B per slot8

    // ldmatrix lane addressing (byte offsets within tile)
    const uint32_t a_ld = (uint32_t)((wm * 16 + (lid & 15)) * ROWB + (lid >> 4) * 16);
    const uint32_t b_ld = (uint32_t)((wn * 16 + ((lid & 7) | ((lid >> 4) << 3))) * ROWB
                                     + (((lid >> 3) & 1) * 16));

    // 4 independent accumulator chains: {even,odd k-step} x {n8 block 0,1}
    float c0[2][4] = {};
    float c1[2][4] = {};

    float4 pa[8], pb[4];
    #pragma unroll
    for (int r = 0; r < 8; ++r) pa[r] = *reinterpret_cast<const float4*>(Aptr + r * 16);
    #pragma unroll
    for (int r = 0; r < 4; ++r) pb[r] = *reinterpret_cast<const float4*>(Bptr + r * 32);

    for (int i = 0; i < NCHUNK; ++i) {
        char* buf = smem + (i & 1) * STAGE;
        const uint32_t bufb = sb + (i & 1) * STAGE;

        // commit prefetched chunk (cvt f32 -> fp16)
        #pragma unroll
        for (int r = 0; r < 8; ++r) cvt_sts(buf, A_OFF + a_st + r * 32, pa[r]);
        #pragma unroll
        for (int r = 0; r < 4; ++r) cvt_sts(buf, B_OFF + b_st + r * 64, pb[r]);
        __syncthreads();
        // (single sync per chunk is safe with double buffering: any warp
        //  still reading buffer b is pre-sync(i); a warp writing b in iter
        //  i+1 is post-sync(i+1) for readers / post-sync(i) for old readers.)

        if (i + 1 < NCHUNK) {
            const int off = (i + 1) * KC;
            #pragma unroll
            for (int r = 0; r < 8; ++r)
                pa[r] = *reinterpret_cast<const float4*>(Aptr + off + r * 16);
            #pragma unroll
            for (int r = 0; r < 4; ++r)
                pb[r] = *reinterpret_cast<const float4*>(Bptr + off + r * 32);
        }

        #pragma unroll
        for (int s = 0; s < KC / 16; ++s) {
            const int p = s & 1;
            uint32_t a[4], b[4];
            ldsm_x4(a, bufb + A_OFF + a_ld + s * 32);
            ldsm_x4(b, bufb + B_OFF + b_ld + s * 32);
            mma16816(c0[p], a, b[0], b[1]);
            mma16816(c1[p], a, b[2], b[3]);
        }
    }

    // epilogue: merge chains, add bias, store
    const int row0 = block_m + wm * 16 + (lid >> 2);
    const int coln = block_n + wn * 16 + 2 * (lid & 3);
    float f0[4], f1[4];
    #pragma unroll
    for (int j = 0; j < 4; ++j) {
        f0[j] = c0[0][j] + c0[1][j];
        f1[j] = c1[0][j] + c1[1][j];
    }
    #pragma unroll
    for (int j = 0; j < 2; ++j) {
        const float* cc = j ? f1 : f0;
        const int n = coln + j * 8;
        float2 bv = *reinterpret_cast<const float2*>(bias + n);
        *reinterpret_cast<float2*>(Y + row0 * NDIM + n) =
            make_float2(cc[0] + bv.x, cc[1] + bv.y);
        *reinterpret_cast<float2*>(Y + (row0 + 8) * NDIM + n) =
            make_float2(cc[2] + bv.x, cc[3] + bv.y);
    }
}

extern "C" void kernel_launch(void* const* d_in, const int* in_sizes, int n_in,
                              void* d_out, int out_size)
{
    const float* x    = (const float*)d_in[0];   // [512, 512]
    const float* w    = (const float*)d_in[1];   // [512, 512] (N, K)
    const float* bias = (const float*)d_in[2];   // [512]
    float* y = (float*)d_out;                    // [512, 512]

    cudaFuncSetAttribute(lns_linear_kernel,
                         cudaFuncAttributeMaxDynamicSharedMemorySize, SMEM_TOTAL);
    dim3 grid(NDIM / BN, BDIM / BM);             // (16, 8) = 128 CTAs, one wave
    lns_linear_kernel<<<grid, NTH, SMEM_TOTAL>>>(x, w, bias, y);
}